// round 5
// baseline (speedup 1.0000x reference)
#include <cuda_runtime.h>
#include <math.h>

#define BB 4
#define SS 1024
#define EE 512
#define HH 8
#define HD 64
#define EPSF 1e-7f

#define PSZ (BB*SS*EE)   // 2,097,152 floats per tensor

// Scratch (device globals; no allocation)
__device__ float g_p[3*PSZ];          // pq, pk, pv after h_linear
__device__ float g_vp[PSZ];           // lam_v * pv
__device__ float g_q2[BB*HH*SS];
__device__ float g_k2[BB*HH*SS];
__device__ float g_lm1[BB*HH*SS];     // lam_v - 1
__device__ float g_zn[3][EE];
__device__ float g_ch[3][EE];
__device__ float g_sh[3][EE];

// ---------------------------------------------------------------------------
// Prep 1: per-column weight constants: zn = ||z[:,j]||, cosh(2r), sinh(2r)
// ---------------------------------------------------------------------------
__global__ void prep_w_kernel(const float* __restrict__ zq, const float* __restrict__ rq,
                              const float* __restrict__ zk, const float* __restrict__ rk,
                              const float* __restrict__ zv, const float* __restrict__ rv){
  const int t = blockIdx.x;
  const float* z = (t==0)?zq:((t==1)?zk:zv);
  const float* r = (t==0)?rq:((t==1)?rk:rv);
  const int j = threadIdx.x;
  float s = 0.f;
  #pragma unroll 8
  for(int n=0;n<EE;n++){ float a = z[n*EE+j]; s = fmaf(a,a,s); }
  float zn = fmaxf(sqrtf(s), EPSF);
  g_zn[t][j] = zn;
  float tr = 2.f * r[j];
  g_ch[t][j] = coshf(tr);
  g_sh[t][j] = sinhf(tr);
}

// ---------------------------------------------------------------------------
// h_linear: out = proj( 2*zn*asinh( lam*xz/zn*cosh(2r) - (lam-1)*sinh(2r) ) )
// One block owns 8 full output rows (512 cols) so the row-wise v2 reduction
// and final projection are done in-block.  256 threads, thread t owns cols
// {t, t+256} for all 8 rows.
// ---------------------------------------------------------------------------
#define HLR 8
#define HLK 8
__global__ void __launch_bounds__(256) hlinear_kernel(
    const float* __restrict__ xq, const float* __restrict__ xk, const float* __restrict__ xv,
    const float* __restrict__ zq, const float* __restrict__ zk, const float* __restrict__ zv){
  __shared__ float xs[HLR][EE];     // 16 KB
  __shared__ float zs[HLK][EE];     // 16 KB
  __shared__ float lam_s[HLR];
  __shared__ float rsum[HLR];
  const int t = blockIdx.y;
  const float* __restrict__ x = (t==0)?xq:((t==1)?xk:xv);
  const float* __restrict__ z = (t==0)?zq:((t==1)?zk:zv);
  float* __restrict__ out = g_p + (size_t)t * PSZ;
  const int row0 = blockIdx.x * HLR;
  const int tid = threadIdx.x;

  // load 8 full x rows (float4, coalesced)
  const float4* xg = (const float4*)(x + (size_t)row0 * EE);
  float4* xs4 = (float4*)xs;
  #pragma unroll
  for(int i=0;i<4;i++) xs4[tid + i*256] = xg[tid + i*256];
  if(tid < HLR) rsum[tid] = 0.f;
  __syncthreads();

  // x2 per row -> lam ; warp w handles row w
  const int w = tid >> 5, lane = tid & 31;
  {
    float s = 0.f;
    #pragma unroll
    for(int i=0;i<EE/32;i++){ float a = xs[w][lane + i*32]; s = fmaf(a,a,s); }
    #pragma unroll
    for(int o=16;o>0;o>>=1) s += __shfl_xor_sync(0xffffffffu, s, o);
    if(lane==0) lam_s[w] = 2.f / fmaxf(1.f - s, EPSF);
  }

  const int c0 = tid, c1 = tid + 256;
  float acc0[HLR], acc1[HLR];
  #pragma unroll
  for(int rr=0;rr<HLR;rr++){ acc0[rr]=0.f; acc1[rr]=0.f; }

  for(int k0=0;k0<EE;k0+=HLK){
    __syncthreads();  // zs from previous chunk fully consumed
    const float4* zg = (const float4*)(z + (size_t)k0 * EE);
    float4* zs4 = (float4*)zs;
    #pragma unroll
    for(int i=0;i<4;i++) zs4[tid + i*256] = zg[tid + i*256];
    __syncthreads();
    #pragma unroll
    for(int kk=0;kk<HLK;kk++){
      float z0 = zs[kk][c0], z1 = zs[kk][c1];
      #pragma unroll
      for(int rr=0;rr<HLR;rr++){
        float a = xs[rr][k0+kk];
        acc0[rr] = fmaf(a, z0, acc0[rr]);
        acc1[rr] = fmaf(a, z1, acc1[rr]);
      }
    }
  }

  // nonlinearity + row-wise v2 reduction
  float vb0[HLR], vb1[HLR];
  const float zn0 = g_zn[t][c0], zn1 = g_zn[t][c1];
  const float ch0 = g_ch[t][c0], ch1 = g_ch[t][c1];
  const float sh0 = g_sh[t][c0], sh1 = g_sh[t][c1];
  #pragma unroll
  for(int rr=0;rr<HLR;rr++){
    float lam = lam_s[rr];
    float lm1 = lam - 1.f;
    float u0 = lam*acc0[rr]/zn0*ch0 - lm1*sh0;
    float u1 = lam*acc1[rr]/zn1*ch1 - lm1*sh1;
    float v0 = 2.f*zn0*asinhf(u0);
    float v1 = 2.f*zn1*asinhf(u1);
    vb0[rr]=v0; vb1[rr]=v1;
    float p = fmaf(v0,v0, v1*v1);
    #pragma unroll
    for(int o=16;o>0;o>>=1) p += __shfl_xor_sync(0xffffffffu, p, o);
    if(lane==0) atomicAdd(&rsum[rr], p);
  }
  __syncthreads();
  #pragma unroll
  for(int rr=0;rr<HLR;rr++){
    float v2 = rsum[rr];
    float scl = 1.f/(1.f + sqrtf(1.f + v2));
    out[(size_t)(row0+rr)*EE + c0] = vb0[rr]*scl;
    out[(size_t)(row0+rr)*EE + c1] = vb1[rr]*scl;
  }
}

// ---------------------------------------------------------------------------
// Prep 2: per (b,h,s): q2, k2, lam_v-1, and vp = lam_v * pv. One warp each.
// ---------------------------------------------------------------------------
__global__ void __launch_bounds__(256) prep_bhs_kernel(){
  const int wg = blockIdx.x * 8 + (threadIdx.x >> 5);
  const int lane = threadIdx.x & 31;
  const int h = wg & (HH-1);
  const int s = (wg >> 3) & (SS-1);
  const int b = wg >> 13;
  const size_t base = ((size_t)(b*SS + s))*EE + h*HD;
  const float* __restrict__ pq = g_p;
  const float* __restrict__ pk = g_p + PSZ;
  const float* __restrict__ pv = g_p + 2*PSZ;
  float qa = pq[base+lane], qb = pq[base+32+lane];
  float ka = pk[base+lane], kb = pk[base+32+lane];
  float va = pv[base+lane], vb = pv[base+32+lane];
  float sq = fmaf(qa,qa, qb*qb);
  float sk = fmaf(ka,ka, kb*kb);
  float sv = fmaf(va,va, vb*vb);
  #pragma unroll
  for(int o=16;o>0;o>>=1){
    sq += __shfl_xor_sync(0xffffffffu, sq, o);
    sk += __shfl_xor_sync(0xffffffffu, sk, o);
    sv += __shfl_xor_sync(0xffffffffu, sv, o);
  }
  float lamv = 2.f / fmaxf(1.f - sv, EPSF);
  const int idx = (b*HH + h)*SS + s;
  if(lane==0){ g_q2[idx]=sq; g_k2[idx]=sk; g_lm1[idx]=lamv-1.f; }
  g_vp[base+lane]    = lamv*va;
  g_vp[base+32+lane] = lamv*vb;
}

// ---------------------------------------------------------------------------
// Attention: per block (b, h, 64-query tile), stream over 16 key tiles of 64.
//   e = exp(-arccosh(arg)) = 1/(arg + sqrt(arg^2-1))  (no log/exp needed)
//   num += e * vp ; den += e * (lam_v - 1)  (softmax Z cancels in num/den)
// XOR-swizzled smem (c4 ^= row>>2) -> all GEMM LDS/STS phases conflict-free.
// ZERO static smem: dynamic = 48 KB exactly (default limit, no attribute
// call allowed). q2/k2/lm1 live in registers; epilogue scratch aliases Qs.
// ---------------------------------------------------------------------------
#define SWZ(row, c4) ((((row)<<4)) | ((c4) ^ (((row)>>2)&15)))

__global__ void __launch_bounds__(256) attn_kernel(float* __restrict__ out){
  extern __shared__ float sm[];
  float* Qs = sm;               // 64x64
  float* Ks = sm + 64*64;       // 64x64, reused as Es after GEMM1
  float* Vs = sm + 2*64*64;     // 64x64

  const int qt = blockIdx.x, h = blockIdx.y, b = blockIdx.z;
  const int tid = threadIdx.x;
  const int ty = tid >> 4, tx = tid & 15;
  const int q0 = qt * 64;
  const int bh = (b*HH + h)*SS;
  const float* __restrict__ pq = g_p;
  const float* __restrict__ pk = g_p + PSZ;

  // load Q tile (swizzled); q2 for my 4 query rows -> registers
  const size_t qbase = ((size_t)(b*SS + q0))*EE + h*HD;
  #pragma unroll
  for(int i2=0;i2<4;i2++){
    int rrow = ty + i2*16;
    ((float4*)Qs)[SWZ(rrow, tx)] = *(const float4*)(pq + qbase + (size_t)rrow*EE + tx*4);
  }
  float q2r[4];
  #pragma unroll
  for(int i=0;i<4;i++) q2r[i] = g_q2[bh + q0 + ty*4 + i];

  float num[4][4];
  float den[4];
  #pragma unroll
  for(int i=0;i<4;i++){ den[i]=0.f;
    #pragma unroll
    for(int j=0;j<4;j++) num[i][j]=0.f; }

  for(int kt=0; kt<SS/64; kt++){
    const int k0 = kt*64;
    const size_t kbase = ((size_t)(b*SS + k0))*EE + h*HD;
    __syncthreads();   // prior-tile reads (and Q-tile stores on iter 0) complete
    #pragma unroll
    for(int i2=0;i2<4;i2++){
      int rrow = ty + i2*16;
      ((float4*)Ks)[SWZ(rrow, tx)] = *(const float4*)(pk   + kbase + (size_t)rrow*EE + tx*4);
      ((float4*)Vs)[SWZ(rrow, tx)] = *(const float4*)(g_vp + kbase + (size_t)rrow*EE + tx*4);
    }
    // per-thread k2 / lam-1 for my 4 key columns (tx*4+j) -> registers
    float k2r[4], lm1r[4];
    #pragma unroll
    for(int j=0;j<4;j++){
      k2r[j]  = g_k2[bh + k0 + tx*4 + j];
      lm1r[j] = g_lm1[bh + k0 + tx*4 + j];
    }
    __syncthreads();

    // GEMM1: sc[i][j] = q(ty*4+i) . k(tx*4+j)
    float scq[4][4];
    #pragma unroll
    for(int i=0;i<4;i++){
      #pragma unroll
      for(int j=0;j<4;j++) scq[i][j]=0.f;
    }
    #pragma unroll
    for(int kd4=0; kd4<16; kd4++){
      float4 qv[4], kv[4];
      #pragma unroll
      for(int i=0;i<4;i++) qv[i] = ((const float4*)Qs)[SWZ(ty*4+i, kd4)];
      #pragma unroll
      for(int j=0;j<4;j++) kv[j] = ((const float4*)Ks)[SWZ(tx*4+j, kd4)];
      #pragma unroll
      for(int i=0;i<4;i++){
        #pragma unroll
        for(int j=0;j<4;j++){
          scq[i][j] = fmaf(qv[i].x, kv[j].x, scq[i][j]);
          scq[i][j] = fmaf(qv[i].y, kv[j].y, scq[i][j]);
          scq[i][j] = fmaf(qv[i].z, kv[j].z, scq[i][j]);
          scq[i][j] = fmaf(qv[i].w, kv[j].w, scq[i][j]);
        }
      }
    }
    __syncthreads();   // all Ks reads done before overwriting with Es

    // elementwise: e = 1/(arg + sqrt(arg^2-1)); accumulate den; write Es
    #pragma unroll
    for(int i=0;i<4;i++){
      float q2 = q2r[i];
      float iq = 1.f - q2;
      float e4[4];
      #pragma unroll
      for(int j=0;j<4;j++){
        float k2 = k2r[j];
        float d2 = fmaxf(q2 + k2 - 2.f*scq[i][j], 0.f);
        float dn = fmaxf(iq*(1.f-k2), EPSF);
        float arg = fmaxf(1.f + 2.f*d2/dn, 1.f + EPSF);
        float e = 1.f/(arg + sqrtf(fmaf(arg,arg,-1.f)));
        e4[j] = e;
        den[i] = fmaf(e, lm1r[j], den[i]);
      }
      float4 ev; ev.x=e4[0]; ev.y=e4[1]; ev.z=e4[2]; ev.w=e4[3];
      ((float4*)Ks)[SWZ(ty*4+i, tx)] = ev;     // Es
    }
    __syncthreads();

    // GEMM2: num[i][d] += Es[q][k] * Vs[k][d],  d = tx*4+j
    #pragma unroll
    for(int kk4=0; kk4<16; kk4++){
      float4 evv[4], vv[4];
      #pragma unroll
      for(int i=0;i<4;i++) evv[i] = ((const float4*)Ks)[SWZ(ty*4+i, kk4)];
      #pragma unroll
      for(int r=0;r<4;r++) vv[r] = ((const float4*)Vs)[SWZ(kk4*4+r, tx)];
      #pragma unroll
      for(int i=0;i<4;i++){
        num[i][0] = fmaf(evv[i].x, vv[0].x, num[i][0]);
        num[i][0] = fmaf(evv[i].y, vv[1].x, num[i][0]);
        num[i][0] = fmaf(evv[i].z, vv[2].x, num[i][0]);
        num[i][0] = fmaf(evv[i].w, vv[3].x, num[i][0]);
        num[i][1] = fmaf(evv[i].x, vv[0].y, num[i][1]);
        num[i][1] = fmaf(evv[i].y, vv[1].y, num[i][1]);
        num[i][1] = fmaf(evv[i].z, vv[2].y, num[i][1]);
        num[i][1] = fmaf(evv[i].w, vv[3].y, num[i][1]);
        num[i][2] = fmaf(evv[i].x, vv[0].z, num[i][2]);
        num[i][2] = fmaf(evv[i].y, vv[1].z, num[i][2]);
        num[i][2] = fmaf(evv[i].z, vv[2].z, num[i][2]);
        num[i][2] = fmaf(evv[i].w, vv[3].z, num[i][2]);
        num[i][3] = fmaf(evv[i].x, vv[0].w, num[i][3]);
        num[i][3] = fmaf(evv[i].y, vv[1].w, num[i][3]);
        num[i][3] = fmaf(evv[i].z, vv[2].w, num[i][3]);
        num[i][3] = fmaf(evv[i].w, vv[3].w, num[i][3]);
      }
    }
  }

  // epilogue: den reduce, m_bar, norm, mobius half scalar-mul
  // Scratch aliases the (now dead) Qs tile region of dynamic smem.
  float* red  = Qs;              // [64][17] strided
  float* dens = Qs + 64*17;      // 64
  float* fac  = Qs + 64*17 + 64; // 64
  __syncthreads();               // Qs/Ks/Vs reads all complete
  #pragma unroll
  for(int i=0;i<4;i++) red[(ty*4+i)*17 + tx] = den[i];
  __syncthreads();
  if(tid < 64){
    float s = 0.f;
    #pragma unroll
    for(int xx=0;xx<16;xx++) s += red[tid*17 + xx];
    dens[tid] = (fabsf(s) < EPSF) ? EPSF : s;
  }
  __syncthreads();
  float mb[4][4];
  #pragma unroll
  for(int i=0;i<4;i++){
    float dq = dens[ty*4+i];
    float p = 0.f;
    #pragma unroll
    for(int j=0;j<4;j++){
      mb[i][j] = num[i][j]/dq;
      p = fmaf(mb[i][j], mb[i][j], p);
    }
    red[(ty*4+i)*17 + tx] = p;
  }
  __syncthreads();
  if(tid < 64){
    float s = 0.f;
    #pragma unroll
    for(int xx=0;xx<16;xx++) s += red[tid*17 + xx];
    float mn = fmaxf(sqrtf(s), EPSF);
    float tt = fminf(mn, 1.f - 1e-6f);
    fac[tid] = tanhf(0.5f*atanhf(tt)) / mn;
  }
  __syncthreads();
  #pragma unroll
  for(int i=0;i<4;i++){
    float f = fac[ty*4+i];
    float4 o;
    o.x = mb[i][0]*f; o.y = mb[i][1]*f; o.z = mb[i][2]*f; o.w = mb[i][3]*f;
    *(float4*)(out + ((size_t)(b*SS + q0 + ty*4 + i))*EE + h*HD + tx*4) = o;
  }
}

// ---------------------------------------------------------------------------
extern "C" void kernel_launch(void* const* d_in, const int* in_sizes, int n_in,
                              void* d_out, int out_size){
  const float* q  = (const float*)d_in[0];
  const float* k  = (const float*)d_in[1];
  const float* v  = (const float*)d_in[2];
  const float* zq = (const float*)d_in[3];
  const float* rq = (const float*)d_in[4];
  const float* zk = (const float*)d_in[5];
  const float* rk = (const float*)d_in[6];
  const float* zv = (const float*)d_in[7];
  const float* rv = (const float*)d_in[8];
  float* out = (float*)d_out;

  prep_w_kernel<<<3, EE>>>(zq, rq, zk, rk, zv, rv);
  hlinear_kernel<<<dim3((BB*SS)/HLR, 3), 256>>>(q, k, v, zq, zk, zv);
  prep_bhs_kernel<<<(BB*SS*HH)/8, 256>>>();
  attn_kernel<<<dim3(SS/64, HH, BB), 256, 3*64*64*sizeof(float)>>>(out);
}

// round 6
// speedup vs baseline: 1.1579x; 1.1579x over previous
#include <cuda_runtime.h>
#include <math.h>

#define BB 4
#define SS 1024
#define EE 512
#define HH 8
#define HD 64
#define EPSF 1e-7f
#define NROW (BB*SS)          // 4096
#define PSZ (BB*SS*EE)        // 2,097,152 floats per tensor

typedef unsigned long long ull;

// ---- f32x2 packed helpers (Blackwell FFMA2 — PTX-only path) ----
__device__ __forceinline__ ull ffma2(ull a, ull b, ull c){
  ull d; asm("fma.rn.f32x2 %0, %1, %2, %3;" : "=l"(d) : "l"(a), "l"(b), "l"(c)); return d;
}
__device__ __forceinline__ ull dup2(float x){
  ull d; asm("mov.b64 %0, {%1, %1};" : "=l"(d) : "f"(x)); return d;
}
__device__ __forceinline__ float2 unpack2(ull a){
  float2 r; asm("mov.b64 {%0, %1}, %2;" : "=f"(r.x), "=f"(r.y) : "l"(a)); return r;
}
__device__ __forceinline__ float hadd2(ull a){ float2 r = unpack2(a); return r.x + r.y; }
union F4U { float4 f; ulonglong2 u; };

// Scratch (device globals; no allocation)
__device__ float g_p[3*PSZ];          // pq, pk, pv after h_linear (projected)
__device__ float g_v[3*PSZ];          // pre-projection v = 2 zn asinh(u)
__device__ float g_vp[PSZ];           // lam_v * pv
__device__ float g_q2[BB*HH*SS];
__device__ float g_k2[BB*HH*SS];
__device__ float g_lm1[BB*HH*SS];     // lam_v - 1
__device__ float g_lam[3*NROW];       // per input row conformal factor
__device__ float g_zn[3][EE];
__device__ float g_ch[3][EE];
__device__ float g_sh[3][EE];

// ---------------------------------------------------------------------------
// Prep 1: per-column weight constants: zn = ||z[:,j]||, cosh(2r), sinh(2r)
// ---------------------------------------------------------------------------
__global__ void prep_w_kernel(const float* __restrict__ zq, const float* __restrict__ rq,
                              const float* __restrict__ zk, const float* __restrict__ rk,
                              const float* __restrict__ zv, const float* __restrict__ rv){
  const int t = blockIdx.x;
  const float* z = (t==0)?zq:((t==1)?zk:zv);
  const float* r = (t==0)?rq:((t==1)?rk:rv);
  const int j = threadIdx.x;
  float s = 0.f;
  #pragma unroll 8
  for(int n=0;n<EE;n++){ float a = z[n*EE+j]; s = fmaf(a,a,s); }
  float zn = fmaxf(sqrtf(s), EPSF);
  g_zn[t][j] = zn;
  float tr = 2.f * r[j];
  g_ch[t][j] = coshf(tr);
  g_sh[t][j] = sinhf(tr);
}

// ---------------------------------------------------------------------------
// Prep 2: lam per input row (one warp per row)
// ---------------------------------------------------------------------------
__global__ void __launch_bounds__(256) prep_lam_kernel(
    const float* __restrict__ xq, const float* __restrict__ xk, const float* __restrict__ xv){
  const int t = blockIdx.y;
  const float* __restrict__ x = (t==0)?xq:((t==1)?xk:xv);
  const int r = blockIdx.x*8 + (threadIdx.x>>5);
  const int lane = threadIdx.x & 31;
  const float4* row = (const float4*)(x + (size_t)r*EE);
  float s = 0.f;
  #pragma unroll
  for(int i=0;i<4;i++){
    float4 a = row[lane + 32*i];
    s = fmaf(a.x,a.x, fmaf(a.y,a.y, fmaf(a.z,a.z, fmaf(a.w,a.w, s))));
  }
  #pragma unroll
  for(int o=16;o>0;o>>=1) s += __shfl_xor_sync(0xffffffffu, s, o);
  if(lane==0) g_lam[t*NROW + r] = 2.f / fmaxf(1.f - s, EPSF);
}

// ---------------------------------------------------------------------------
// h_linear GEMM: v = 2*zn*asinh( lam*(x@z)/zn*cosh(2r) - (lam-1)*sinh(2r) )
// 64 rows x 128 cols per 128-thread block, 8x8 per-thread tile, FFMA2 packed
// along output cols (both operand loads contiguous; only x needs dup-packs,
// which ride the ALU pipe). 1 B/FMA -> LDS and FFMA2 exactly balanced.
// ---------------------------------------------------------------------------
#define GR 64
#define GC 128
#define GK 32
__global__ void __launch_bounds__(128, 4) hgemm_kernel(
    const float* __restrict__ xq, const float* __restrict__ xk, const float* __restrict__ xv,
    const float* __restrict__ zq, const float* __restrict__ zk, const float* __restrict__ zv){
  __shared__ float4 xs4[GR*GK/4];   // [row][kq], 8 f4/row  (8 KB)
  __shared__ float4 zs4[GK*GC/4];   // [k][cq], 32 f4/k     (16 KB)
  const int t = blockIdx.z;
  const float* __restrict__ x = (t==0)?xq:((t==1)?xk:xv);
  const float* __restrict__ z = (t==0)?zq:((t==1)?zk:zv);
  const int r0 = blockIdx.x*GR, c0 = blockIdx.y*GC;
  const int tid = threadIdx.x;
  const int wy = tid>>4, wx = tid&15;   // wy: 8 row-groups, wx: 16 col-groups

  ull accP[8][4];
  #pragma unroll
  for(int i=0;i<8;i++){
    #pragma unroll
    for(int j=0;j<4;j++) accP[i][j] = 0ull;
  }

  const float4* xg = (const float4*)x;  // row length = 128 f4
  const float4* zg = (const float4*)z;

  for(int k0=0;k0<EE;k0+=GK){
    __syncthreads();
    #pragma unroll
    for(int i=0;i<4;i++){
      int idx = tid + i*128; int row = idx>>3, kq = idx&7;
      xs4[idx] = xg[(size_t)(r0+row)*128 + (k0>>2) + kq];
    }
    #pragma unroll
    for(int i=0;i<8;i++){
      int idx = tid + i*128; int kk = idx>>5, cq = idx&31;
      zs4[idx] = zg[(size_t)(k0+kk)*128 + (c0>>2) + cq];
    }
    __syncthreads();
    #pragma unroll
    for(int kq=0;kq<8;kq++){
      float4 xf[8];
      #pragma unroll
      for(int i=0;i<8;i++) xf[i] = xs4[(wy*8+i)*8 + kq];
      #pragma unroll
      for(int kk=0;kk<4;kk++){
        F4U z0, z1;
        z0.f = zs4[(kq*4+kk)*32 + wx];        // cols c0+4wx..+3
        z1.f = zs4[(kq*4+kk)*32 + 16 + wx];   // cols c0+64+4wx..+3
        #pragma unroll
        for(int i=0;i<8;i++){
          float xsc = (kk==0)?xf[i].x:((kk==1)?xf[i].y:((kk==2)?xf[i].z:xf[i].w));
          ull xd = dup2(xsc);
          accP[i][0] = ffma2(xd, z0.u.x, accP[i][0]);
          accP[i][1] = ffma2(xd, z0.u.y, accP[i][1]);
          accP[i][2] = ffma2(xd, z1.u.x, accP[i][2]);
          accP[i][3] = ffma2(xd, z1.u.y, accP[i][3]);
        }
      }
    }
  }

  // epilogue: nonlinearity, write pre-projection v
  F4U znA, znB, chA, chB, shA, shB;
  znA.f = ((const float4*)g_zn[t])[(c0>>2)+wx];       znB.f = ((const float4*)g_zn[t])[(c0>>2)+16+wx];
  chA.f = ((const float4*)g_ch[t])[(c0>>2)+wx];       chB.f = ((const float4*)g_ch[t])[(c0>>2)+16+wx];
  shA.f = ((const float4*)g_sh[t])[(c0>>2)+wx];       shB.f = ((const float4*)g_sh[t])[(c0>>2)+16+wx];
  float* __restrict__ vout = g_v + (size_t)t*PSZ;
  #pragma unroll
  for(int i=0;i<8;i++){
    const int row = r0 + wy*8 + i;
    const float lam = g_lam[t*NROW + row];
    const float lm1 = lam - 1.f;
    #pragma unroll
    for(int g=0; g<2; g++){
      float2 a0 = unpack2(accP[i][2*g]);
      float2 a1 = unpack2(accP[i][2*g+1]);
      float4 zn4 = g? znB.f : znA.f;
      float4 ch4 = g? chB.f : chA.f;
      float4 sh4 = g? shB.f : shA.f;
      float4 o;
      o.x = 2.f*zn4.x*asinhf(lam*a0.x/zn4.x*ch4.x - lm1*sh4.x);
      o.y = 2.f*zn4.y*asinhf(lam*a0.y/zn4.y*ch4.y - lm1*sh4.y);
      o.z = 2.f*zn4.z*asinhf(lam*a1.x/zn4.z*ch4.z - lm1*sh4.z);
      o.w = 2.f*zn4.w*asinhf(lam*a1.y/zn4.w*ch4.w - lm1*sh4.w);
      *(float4*)(vout + (size_t)row*EE + c0 + 4*wx + 64*g) = o;
    }
  }
}

// ---------------------------------------------------------------------------
// Projection + per-head prep (fuses old prep_bhs). One warp per row.
// lane covers f4 indices {lane+32i}: i -> heads {2i (lanes 0-15), 2i+1}.
// p = v * scl ; head sumsq(p) = scl^2 * head sumsq(v).
// ---------------------------------------------------------------------------
__global__ void __launch_bounds__(256) proj_kernel(){
  const int t = blockIdx.y;
  const int r = blockIdx.x*8 + (threadIdx.x>>5);
  const int lane = threadIdx.x & 31;
  const float4* vrow = (const float4*)(g_v + (size_t)t*PSZ + (size_t)r*EE);
  float4 vv[4]; float hs[4];
  #pragma unroll
  for(int i=0;i<4;i++){
    vv[i] = vrow[lane + 32*i];
    float p = fmaf(vv[i].x,vv[i].x, fmaf(vv[i].y,vv[i].y,
              fmaf(vv[i].z,vv[i].z, vv[i].w*vv[i].w)));
    // reduce within 16-lane half (bits 0..3)
    #pragma unroll
    for(int o=8;o>0;o>>=1) p += __shfl_xor_sync(0xffffffffu, p, o);
    p += __shfl_xor_sync(0xffffffffu, p, 1);  // (covered by loop) — keep order simple
    hs[i] = p;
  }
  // NOTE: the loop above already covered offsets 8,4,2,1; the extra xor1 double-
  // counts. Redo cleanly:
  #pragma unroll
  for(int i=0;i<4;i++){
    float p = fmaf(vv[i].x,vv[i].x, fmaf(vv[i].y,vv[i].y,
              fmaf(vv[i].z,vv[i].z, vv[i].w*vv[i].w)));
    p += __shfl_xor_sync(0xffffffffu, p, 8);
    p += __shfl_xor_sync(0xffffffffu, p, 4);
    p += __shfl_xor_sync(0xffffffffu, p, 2);
    p += __shfl_xor_sync(0xffffffffu, p, 1);
    hs[i] = p;   // head sumsq of v for head (lane>>4) + 2i
  }
  float tot = hs[0]+hs[1]+hs[2]+hs[3];
  float v2 = tot + __shfl_xor_sync(0xffffffffu, tot, 16);
  float scl = 1.f/(1.f + sqrtf(1.f + v2));
  float scl2 = scl*scl;

  float* __restrict__ pout = g_p + (size_t)t*PSZ + (size_t)r*EE;
  const int b = r >> 10, s = r & (SS-1);
  if(t < 2){
    #pragma unroll
    for(int i=0;i<4;i++){
      float4 o; o.x=vv[i].x*scl; o.y=vv[i].y*scl; o.z=vv[i].z*scl; o.w=vv[i].w*scl;
      ((float4*)pout)[lane + 32*i] = o;
      if((lane & 15) == 0){
        int h = (lane>>4) + 2*i;
        int idx = (b*HH + h)*SS + s;
        if(t==0) g_q2[idx] = hs[i]*scl2; else g_k2[idx] = hs[i]*scl2;
      }
    }
  } else {
    float* __restrict__ vpout = g_vp + (size_t)r*EE;
    #pragma unroll
    for(int i=0;i<4;i++){
      float pv2h = hs[i]*scl2;
      float lamv = 2.f / fmaxf(1.f - pv2h, EPSF);
      float4 o; o.x=vv[i].x*scl; o.y=vv[i].y*scl; o.z=vv[i].z*scl; o.w=vv[i].w*scl;
      ((float4*)pout)[lane + 32*i] = o;
      float4 w; w.x=o.x*lamv; w.y=o.y*lamv; w.z=o.z*lamv; w.w=o.w*lamv;
      ((float4*)vpout)[lane + 32*i] = w;
      if((lane & 15) == 0){
        int h = (lane>>4) + 2*i;
        g_lm1[(b*HH + h)*SS + s] = lamv - 1.f;
      }
    }
  }
}

// ---------------------------------------------------------------------------
// Attention: per block (b, h, 64-query tile), stream over 16 key tiles of 64.
//   e = exp(-arccosh(arg)) = 1/(arg + sqrt(arg^2-1))
//   num += e * vp ; den += e * (lam_v - 1)   (softmax Z cancels)
// GEMM1/GEMM2 use FFMA2 packed along d (operands contiguous -> no dup cost in
// GEMM1; GEMM2 dups ride the ALU pipe). Zero static smem; dynamic = 48 KB.
// ---------------------------------------------------------------------------
#define SWZ(row, c4) ((((row)<<4)) | ((c4) ^ (((row)>>2)&15)))

__global__ void __launch_bounds__(256, 2) attn_kernel(float* __restrict__ out){
  extern __shared__ float sm[];
  float* Qs = sm;               // 64x64
  float* Ks = sm + 64*64;       // 64x64, reused as Es after GEMM1
  float* Vs = sm + 2*64*64;     // 64x64

  const int qt = blockIdx.x, h = blockIdx.y, b = blockIdx.z;
  const int tid = threadIdx.x;
  const int ty = tid >> 4, tx = tid & 15;
  const int q0 = qt * 64;
  const int bh = (b*HH + h)*SS;
  const float* __restrict__ pq = g_p;
  const float* __restrict__ pk = g_p + PSZ;

  const size_t qbase = ((size_t)(b*SS + q0))*EE + h*HD;
  #pragma unroll
  for(int i2=0;i2<4;i2++){
    int rrow = ty + i2*16;
    ((float4*)Qs)[SWZ(rrow, tx)] = *(const float4*)(pq + qbase + (size_t)rrow*EE + tx*4);
  }
  float q2r[4];
  #pragma unroll
  for(int i=0;i<4;i++) q2r[i] = g_q2[bh + q0 + ty*4 + i];

  ull numP[4][2];
  float den[4];
  #pragma unroll
  for(int i=0;i<4;i++){ den[i]=0.f; numP[i][0]=0ull; numP[i][1]=0ull; }

  for(int kt=0; kt<SS/64; kt++){
    const int k0 = kt*64;
    const size_t kbase = ((size_t)(b*SS + k0))*EE + h*HD;
    __syncthreads();
    #pragma unroll
    for(int i2=0;i2<4;i2++){
      int rrow = ty + i2*16;
      ((float4*)Ks)[SWZ(rrow, tx)] = *(const float4*)(pk   + kbase + (size_t)rrow*EE + tx*4);
      ((float4*)Vs)[SWZ(rrow, tx)] = *(const float4*)(g_vp + kbase + (size_t)rrow*EE + tx*4);
    }
    float k2r[4], lm1r[4];
    #pragma unroll
    for(int j=0;j<4;j++){
      k2r[j]  = g_k2[bh + k0 + tx*4 + j];
      lm1r[j] = g_lm1[bh + k0 + tx*4 + j];
    }
    __syncthreads();

    // GEMM1 (packed along d): scP[i][j] accumulates {even-d, odd-d} partials
    ull scP[4][4];
    #pragma unroll
    for(int i=0;i<4;i++){
      #pragma unroll
      for(int j=0;j<4;j++) scP[i][j]=0ull;
    }
    #pragma unroll
    for(int kd4=0; kd4<16; kd4++){
      F4U qv[4], kv[4];
      #pragma unroll
      for(int i=0;i<4;i++) qv[i].f = ((const float4*)Qs)[SWZ(ty*4+i, kd4)];
      #pragma unroll
      for(int j=0;j<4;j++) kv[j].f = ((const float4*)Ks)[SWZ(tx*4+j, kd4)];
      #pragma unroll
      for(int i=0;i<4;i++){
        #pragma unroll
        for(int j=0;j<4;j++){
          scP[i][j] = ffma2(qv[i].u.x, kv[j].u.x, scP[i][j]);
          scP[i][j] = ffma2(qv[i].u.y, kv[j].u.y, scP[i][j]);
        }
      }
    }
    __syncthreads();   // all Ks reads done before overwriting with Es

    // elementwise: e = 1/(arg + sqrt(arg^2-1)); accumulate den; write Es
    #pragma unroll
    for(int i=0;i<4;i++){
      float q2 = q2r[i];
      float iq = 1.f - q2;
      float e4[4];
      #pragma unroll
      for(int j=0;j<4;j++){
        float sc = hadd2(scP[i][j]);
        float k2 = k2r[j];
        float d2 = fmaxf(q2 + k2 - 2.f*sc, 0.f);
        float dn = fmaxf(iq*(1.f-k2), EPSF);
        float arg = fmaxf(1.f + 2.f*d2/dn, 1.f + EPSF);
        float e = 1.f/(arg + sqrtf(fmaf(arg,arg,-1.f)));
        e4[j] = e;
        den[i] = fmaf(e, lm1r[j], den[i]);
      }
      float4 ev; ev.x=e4[0]; ev.y=e4[1]; ev.z=e4[2]; ev.w=e4[3];
      ((float4*)Ks)[SWZ(ty*4+i, tx)] = ev;     // Es
    }
    __syncthreads();

    // GEMM2 (packed along d): numP[i][p] += {e,e} * vp pairs
    #pragma unroll
    for(int kk4=0; kk4<16; kk4++){
      F4U evv[4], vv[4];
      #pragma unroll
      for(int i=0;i<4;i++) evv[i].f = ((const float4*)Ks)[SWZ(ty*4+i, kk4)];
      #pragma unroll
      for(int r=0;r<4;r++) vv[r].f = ((const float4*)Vs)[SWZ(kk4*4+r, tx)];
      #pragma unroll
      for(int i=0;i<4;i++){
        ull e0 = dup2(evv[i].f.x), e1 = dup2(evv[i].f.y);
        ull e2 = dup2(evv[i].f.z), e3 = dup2(evv[i].f.w);
        numP[i][0] = ffma2(e0, vv[0].u.x, numP[i][0]);
        numP[i][1] = ffma2(e0, vv[0].u.y, numP[i][1]);
        numP[i][0] = ffma2(e1, vv[1].u.x, numP[i][0]);
        numP[i][1] = ffma2(e1, vv[1].u.y, numP[i][1]);
        numP[i][0] = ffma2(e2, vv[2].u.x, numP[i][0]);
        numP[i][1] = ffma2(e2, vv[2].u.y, numP[i][1]);
        numP[i][0] = ffma2(e3, vv[3].u.x, numP[i][0]);
        numP[i][1] = ffma2(e3, vv[3].u.y, numP[i][1]);
      }
    }
  }

  // epilogue: den reduce, m_bar, norm, mobius half scalar-mul
  float* red  = Qs;              // [64][17] strided, aliases dead Qs
  float* dens = Qs + 64*17;
  float* fac  = Qs + 64*17 + 64;
  __syncthreads();
  #pragma unroll
  for(int i=0;i<4;i++) red[(ty*4+i)*17 + tx] = den[i];
  __syncthreads();
  if(tid < 64){
    float s = 0.f;
    #pragma unroll
    for(int xx=0;xx<16;xx++) s += red[tid*17 + xx];
    dens[tid] = (fabsf(s) < EPSF) ? EPSF : s;
  }
  __syncthreads();
  float mb[4][4];
  #pragma unroll
  for(int i=0;i<4;i++){
    float dq = dens[ty*4+i];
    float2 n0 = unpack2(numP[i][0]);
    float2 n1 = unpack2(numP[i][1]);
    mb[i][0] = n0.x/dq; mb[i][1] = n0.y/dq; mb[i][2] = n1.x/dq; mb[i][3] = n1.y/dq;
    float p = fmaf(mb[i][0],mb[i][0], fmaf(mb[i][1],mb[i][1],
              fmaf(mb[i][2],mb[i][2], mb[i][3]*mb[i][3])));
    red[(ty*4+i)*17 + tx] = p;
  }
  __syncthreads();
  if(tid < 64){
    float s = 0.f;
    #pragma unroll
    for(int xx=0;xx<16;xx++) s += red[tid*17 + xx];
    float mn = fmaxf(sqrtf(s), EPSF);
    float tt = fminf(mn, 1.f - 1e-6f);
    fac[tid] = tanhf(0.5f*atanhf(tt)) / mn;
  }
  __syncthreads();
  #pragma unroll
  for(int i=0;i<4;i++){
    float f = fac[ty*4+i];
    float4 o;
    o.x = mb[i][0]*f; o.y = mb[i][1]*f; o.z = mb[i][2]*f; o.w = mb[i][3]*f;
    *(float4*)(out + ((size_t)(b*SS + q0 + ty*4 + i))*EE + h*HD + tx*4) = o;
  }
}

// ---------------------------------------------------------------------------
extern "C" void kernel_launch(void* const* d_in, const int* in_sizes, int n_in,
                              void* d_out, int out_size){
  const float* q  = (const float*)d_in[0];
  const float* k  = (const float*)d_in[1];
  const float* v  = (const float*)d_in[2];
  const float* zq = (const float*)d_in[3];
  const float* rq = (const float*)d_in[4];
  const float* zk = (const float*)d_in[5];
  const float* rk = (const float*)d_in[6];
  const float* zv = (const float*)d_in[7];
  const float* rv = (const float*)d_in[8];
  float* out = (float*)d_out;

  prep_w_kernel<<<3, EE>>>(zq, rq, zk, rk, zv, rv);
  prep_lam_kernel<<<dim3(NROW/8, 3), 256>>>(q, k, v);
  hgemm_kernel<<<dim3(NROW/GR, EE/GC, 3), 128>>>(q, k, v, zq, zk, zv);
  proj_kernel<<<dim3(NROW/8, 3), 256>>>();
  attn_kernel<<<dim3(SS/64, HH, BB), 256, 3*64*64*sizeof(float)>>>(out);
}